// round 1
// baseline (speedup 1.0000x reference)
#include <cuda_runtime.h>
#include <cuda_bf16.h>
#include <math.h>

// Problem: Attention_33492154974379
//   x: [B=8, T=2048, D=1024] fp32
//   out = concat( att_vec [B,T,D], att_weights [B,T,T] )  (reference return order)
// scores = x @ x^T, strictly-lower kept, diag+upper = -1e9, softmax rows,
// att_vec = weights @ x.

#define B_ 8
#define T_ 2048
#define D_ 1024
#define NEG_INF_ (-1.0e9f)
#define BLK 64

// ---------------------------------------------------------------------------
// Pass 1: masked scores -> weights buffer (pre-softmax).
// Tiles strictly above the diagonal are filled with -1e9 (no GEMM).
// ---------------------------------------------------------------------------
__global__ __launch_bounds__(256) void scores_kernel(const float* __restrict__ x,
                                                     float* __restrict__ w) {
    const int b  = blockIdx.z;
    const int ti = blockIdx.y;   // row tile
    const int tj = blockIdx.x;   // col tile
    const int tid = threadIdx.x; // 256

    float* wb = w + (size_t)b * T_ * T_;
    const int gi0 = ti * BLK, gj0 = tj * BLK;

    if (tj > ti) {
        // Entire tile masked: coalesced -1e9 fill. 64x64 = 4096 floats / 256 thr.
        #pragma unroll
        for (int t = 0; t < 16; ++t) {
            int idx = tid + t * 256;
            int r = idx >> 6, c = idx & 63;
            wb[(size_t)(gi0 + r) * T_ + gj0 + c] = NEG_INF_;
        }
        return;
    }

    __shared__ float As[16][BLK + 1];
    __shared__ float Bs[16][BLK + 1];

    const float* xa = x + (size_t)b * T_ * D_ + (size_t)gi0 * D_;
    const float* xb = x + (size_t)b * T_ * D_ + (size_t)gj0 * D_;

    float acc[4][4] = {};
    const int lr = tid >> 2;          // 0..63 (row within tile for loads)
    const int lc = (tid & 3) * 4;     // 0,4,8,12 (k offset for loads)
    const int tx = tid & 15;          // output col group
    const int ty = tid >> 4;          // output row group

    for (int kk = 0; kk < D_; kk += 16) {
        float4 a  = *(const float4*)(xa + (size_t)lr * D_ + kk + lc);
        float4 bv = *(const float4*)(xb + (size_t)lr * D_ + kk + lc);
        As[lc + 0][lr] = a.x;  As[lc + 1][lr] = a.y;
        As[lc + 2][lr] = a.z;  As[lc + 3][lr] = a.w;
        Bs[lc + 0][lr] = bv.x; Bs[lc + 1][lr] = bv.y;
        Bs[lc + 2][lr] = bv.z; Bs[lc + 3][lr] = bv.w;
        __syncthreads();
        #pragma unroll
        for (int k = 0; k < 16; ++k) {
            float ra[4], rb[4];
            #pragma unroll
            for (int u = 0; u < 4; ++u) { ra[u] = As[k][ty * 4 + u]; rb[u] = Bs[k][tx * 4 + u]; }
            #pragma unroll
            for (int u = 0; u < 4; ++u)
                #pragma unroll
                for (int v = 0; v < 4; ++v)
                    acc[u][v] = fmaf(ra[u], rb[v], acc[u][v]);
        }
        __syncthreads();
    }

    #pragma unroll
    for (int u = 0; u < 4; ++u) {
        const int gi = gi0 + ty * 4 + u;
        #pragma unroll
        for (int v = 0; v < 4; ++v) {
            const int gj = gj0 + tx * 4 + v;
            wb[(size_t)gi * T_ + gj] = (gj < gi) ? acc[u][v] : NEG_INF_;
        }
    }
}

// ---------------------------------------------------------------------------
// Pass 2: in-place row softmax over T=2048. One block per row.
// Row 0 (all -1e9) naturally yields uniform 1/T, matching the reference.
// Masked entries for i>=1 underflow exp() to exactly 0.0f, same as fp32 JAX.
// ---------------------------------------------------------------------------
__global__ __launch_bounds__(256) void softmax_kernel(float* __restrict__ w) {
    const int row = blockIdx.x;            // 0 .. B*T-1
    float* p = w + (size_t)row * T_;
    const int tid = threadIdx.x;

    float v[8];
    float m = -INFINITY;
    #pragma unroll
    for (int k = 0; k < 8; ++k) { v[k] = p[tid + k * 256]; m = fmaxf(m, v[k]); }

    __shared__ float red[256];
    red[tid] = m; __syncthreads();
    #pragma unroll
    for (int s = 128; s > 0; s >>= 1) {
        if (tid < s) red[tid] = fmaxf(red[tid], red[tid + s]);
        __syncthreads();
    }
    m = red[0];
    __syncthreads();

    float sum = 0.0f;
    #pragma unroll
    for (int k = 0; k < 8; ++k) { v[k] = expf(v[k] - m); sum += v[k]; }

    red[tid] = sum; __syncthreads();
    #pragma unroll
    for (int s = 128; s > 0; s >>= 1) {
        if (tid < s) red[tid] += red[tid + s];
        __syncthreads();
    }
    const float inv = 1.0f / red[0];

    #pragma unroll
    for (int k = 0; k < 8; ++k) p[tid + k * 256] = v[k] * inv;
}

// ---------------------------------------------------------------------------
// Pass 3: att_vec = W @ X.  Output tile 64 (rows) x 64 (D cols).
// For row-block ti>0 the weights are exactly zero for k >= (ti+1)*64, so the
// K loop is truncated. Row-block 0 contains the dense row 0 -> full K.
// ---------------------------------------------------------------------------
__global__ __launch_bounds__(256) void av_kernel(const float* __restrict__ w,
                                                 const float* __restrict__ x,
                                                 float* __restrict__ o) {
    const int b  = blockIdx.z;
    const int ti = blockIdx.y;   // row tile (T)
    const int tj = blockIdx.x;   // col tile (D)
    const int tid = threadIdx.x;

    const float* wb = w + (size_t)b * T_ * T_;
    const float* xb = x + (size_t)b * T_ * D_;
    float* ob = o + (size_t)b * T_ * D_;

    const int gi0 = ti * BLK, gj0 = tj * BLK;
    const int kmax = (ti == 0) ? T_ : (ti + 1) * BLK;

    __shared__ float As[16][BLK + 1];
    __shared__ float Bs[16][BLK + 1];

    float acc[4][4] = {};
    const int lr = tid >> 2;
    const int lc = (tid & 3) * 4;
    const int bk = tid >> 4;          // 0..15 (k row of X chunk)
    const int bj = (tid & 15) * 4;    // 0..60 (D col)
    const int tx = tid & 15;
    const int ty = tid >> 4;

    for (int kk = 0; kk < kmax; kk += 16) {
        float4 a  = *(const float4*)(wb + (size_t)(gi0 + lr) * T_ + kk + lc);
        As[lc + 0][lr] = a.x; As[lc + 1][lr] = a.y;
        As[lc + 2][lr] = a.z; As[lc + 3][lr] = a.w;
        float4 bv = *(const float4*)(xb + (size_t)(kk + bk) * D_ + gj0 + bj);
        Bs[bk][bj + 0] = bv.x; Bs[bk][bj + 1] = bv.y;
        Bs[bk][bj + 2] = bv.z; Bs[bk][bj + 3] = bv.w;
        __syncthreads();
        #pragma unroll
        for (int k = 0; k < 16; ++k) {
            float ra[4], rb[4];
            #pragma unroll
            for (int u = 0; u < 4; ++u) { ra[u] = As[k][ty * 4 + u]; rb[u] = Bs[k][tx * 4 + u]; }
            #pragma unroll
            for (int u = 0; u < 4; ++u)
                #pragma unroll
                for (int v = 0; v < 4; ++v)
                    acc[u][v] = fmaf(ra[u], rb[v], acc[u][v]);
        }
        __syncthreads();
    }

    #pragma unroll
    for (int u = 0; u < 4; ++u) {
        const int gi = gi0 + ty * 4 + u;
        #pragma unroll
        for (int v = 0; v < 4; ++v)
            ob[(size_t)gi * D_ + gj0 + tx * 4 + v] = acc[u][v];
    }
}

// ---------------------------------------------------------------------------
extern "C" void kernel_launch(void* const* d_in, const int* in_sizes, int n_in,
                              void* d_out, int out_size) {
    const float* x = (const float*)d_in[0];
    float* att_vec = (float*)d_out;                              // [B,T,D]
    float* att_w   = (float*)d_out + (size_t)B_ * T_ * D_;       // [B,T,T]

    (void)in_sizes; (void)n_in; (void)out_size;

    dim3 g1(T_ / BLK, T_ / BLK, B_);     // 32 x 32 x 8
    scores_kernel<<<g1, 256>>>(x, att_w);

    softmax_kernel<<<B_ * T_, 256>>>(att_w);

    dim3 g3(D_ / BLK, T_ / BLK, B_);     // 16 x 32 x 8
    av_kernel<<<g3, 256>>>(att_w, x, att_vec);
}

// round 2
// speedup vs baseline: 2.9788x; 2.9788x over previous
#include <cuda_runtime.h>
#include <cuda_bf16.h>
#include <math.h>
#include <stdint.h>

// Attention_33492154974379:  x [B=8, T=2048, D=1024] fp32
// out = concat(att_vec [B,T,D], att_weights [B,T,T])
// scores = x@x^T, strict-lower kept, diag+upper=-1e9, softmax, av = W@x.
// bf16 hi/lo split (3-term) tensor-core GEMMs, fp32 accumulate.

#define B_ 8
#define T_ 2048
#define D_ 1024
#define NEG_INF_ (-1.0e9f)

// ---- static scratch (allocation-free rule: __device__ globals) ----
__device__ __nv_bfloat16 g_xhi[(size_t)B_ * T_ * D_];
__device__ __nv_bfloat16 g_xlo[(size_t)B_ * T_ * D_];
__device__ __nv_bfloat16 g_xthi[(size_t)B_ * D_ * T_];   // x^T  [B,D,T]
__device__ __nv_bfloat16 g_xtlo[(size_t)B_ * D_ * T_];
__device__ __nv_bfloat16 g_whi[(size_t)B_ * T_ * T_];
__device__ __nv_bfloat16 g_wlo[(size_t)B_ * T_ * T_];

// ---- smem geometry: 4 tiles (Ahi,Alo,Bhi,Blo) of 128 x 32 bf16, stride 40 ----
#define LDS_ 40
#define TILE_E (128 * LDS_)      // 5120 elems
#define STAGE_E (4 * TILE_E)     // 20480 elems
#define SMEM_BYTES (2 * STAGE_E * 2)  // 81920 bytes (double buffered)

__device__ __forceinline__ void ldsm4(uint32_t* r, uint32_t a) {
    asm volatile("ldmatrix.sync.aligned.m8n8.x4.shared.b16 {%0,%1,%2,%3}, [%4];"
                 : "=r"(r[0]), "=r"(r[1]), "=r"(r[2]), "=r"(r[3]) : "r"(a));
}
__device__ __forceinline__ void mma16816(float* d, const uint32_t* a, const uint32_t* b) {
    asm volatile("mma.sync.aligned.m16n8k16.row.col.f32.bf16.bf16.f32 "
                 "{%0,%1,%2,%3}, {%4,%5,%6,%7}, {%8,%9}, {%0,%1,%2,%3};"
                 : "+f"(d[0]), "+f"(d[1]), "+f"(d[2]), "+f"(d[3])
                 : "r"(a[0]), "r"(a[1]), "r"(a[2]), "r"(a[3]), "r"(b[0]), "r"(b[1]));
}
__device__ __forceinline__ void cpa16(uint32_t d, const void* s) {
    asm volatile("cp.async.cg.shared.global [%0], [%1], 16;" :: "r"(d), "l"(s) : "memory");
}
__device__ __forceinline__ void cpcommit() { asm volatile("cp.async.commit_group;" ::: "memory"); }
template <int N>
__device__ __forceinline__ void cpwait() { asm volatile("cp.async.wait_group %0;" :: "n"(N) : "memory"); }

// ---------------------------------------------------------------------------
// Pass 0: x -> (hi,lo) and transposed (hi,lo)
// ---------------------------------------------------------------------------
__global__ __launch_bounds__(256) void convert_kernel(const float* __restrict__ x) {
    __shared__ float tile[32][33];
    const int b = blockIdx.z;
    const int t0 = blockIdx.y * 32, d0 = blockIdx.x * 32;
    const int tx = threadIdx.x, ty = threadIdx.y;  // (32, 8)
    const float* xb = x + (size_t)b * T_ * D_;

    #pragma unroll
    for (int k = 0; k < 4; ++k) {
        const int r = ty + k * 8;
        const float v = xb[(size_t)(t0 + r) * D_ + d0 + tx];
        tile[r][tx] = v;
        __nv_bfloat16 hi = __float2bfloat16_rn(v);
        __nv_bfloat16 lo = __float2bfloat16_rn(v - __bfloat162float(hi));
        const size_t o = (size_t)b * T_ * D_ + (size_t)(t0 + r) * D_ + d0 + tx;
        g_xhi[o] = hi; g_xlo[o] = lo;
    }
    __syncthreads();
    #pragma unroll
    for (int k = 0; k < 4; ++k) {
        const int r = ty + k * 8;                 // local d index
        const float v = tile[tx][r];              // (d = d0+r, t = t0+tx)
        __nv_bfloat16 hi = __float2bfloat16_rn(v);
        __nv_bfloat16 lo = __float2bfloat16_rn(v - __bfloat162float(hi));
        const size_t o = (size_t)b * D_ * T_ + (size_t)(d0 + r) * T_ + t0 + tx;
        g_xthi[o] = hi; g_xtlo[o] = lo;
    }
}

// ---------------------------------------------------------------------------
// Shared MMA mainloop: C[128x128] += 3-term split GEMM over K (chunks of 32).
// A,B row-major [rows][K] with leading dim ldk; B holds the [N][K] operand.
// ---------------------------------------------------------------------------
__device__ __forceinline__ void gemm_mainloop(
    const __nv_bfloat16* __restrict__ Ahi, const __nv_bfloat16* __restrict__ Alo,
    const __nv_bfloat16* __restrict__ Bhi, const __nv_bfloat16* __restrict__ Blo,
    int ldk, int kmax, float acc[4][4][4])
{
    extern __shared__ __nv_bfloat16 sm[];
    const int tid = threadIdx.x;
    const int lane = tid & 31, warp = tid >> 5;
    const int wm = (warp >> 2) * 64, wn = (warp & 3) * 32;
    const uint32_t smem_u32 = (uint32_t)__cvta_generic_to_shared(sm);

    // copy mapping: threads [0..63]->tile0, [64..127]->tile1, ...
    const int tile = tid >> 6;
    const __nv_bfloat16* sp = (tile == 0) ? Ahi : (tile == 1) ? Alo : (tile == 2) ? Bhi : Blo;
    const int crow0 = (tid & 63) >> 2;  // + t*16
    const int cc = tid & 3;
    const uint32_t dtile = (uint32_t)(tile * TILE_E) * 2;

    const int nchunks = kmax >> 5;

    // prologue: stage 0
    {
        #pragma unroll
        for (int t = 0; t < 8; ++t) {
            const int row = crow0 + t * 16;
            cpa16(smem_u32 + dtile + (uint32_t)(row * LDS_ + cc * 8) * 2,
                  sp + (size_t)row * ldk + cc * 8);
        }
        cpcommit();
    }

    for (int i = 0; i < nchunks; ++i) {
        const int s = i & 1;
        if (i + 1 < nchunks) {
            const int kk = (i + 1) << 5;
            const uint32_t dst0 = smem_u32 + (uint32_t)((s ^ 1) * STAGE_E) * 2 + dtile;
            #pragma unroll
            for (int t = 0; t < 8; ++t) {
                const int row = crow0 + t * 16;
                cpa16(dst0 + (uint32_t)(row * LDS_ + cc * 8) * 2,
                      sp + (size_t)row * ldk + kk + cc * 8);
            }
            cpcommit();
            cpwait<1>();
        } else {
            cpwait<0>();
        }
        __syncthreads();

        const uint32_t stA   = smem_u32 + (uint32_t)(s * STAGE_E) * 2;
        const uint32_t stAlo = stA + TILE_E * 2;
        const uint32_t stB   = stA + 2 * TILE_E * 2;
        const uint32_t stBlo = stA + 3 * TILE_E * 2;

        #pragma unroll
        for (int s2 = 0; s2 < 2; ++s2) {
            uint32_t ahi[4][4], alo[4][4], bhi[4][2], blo[4][2];
            const int ar = wm + (lane & 15);
            const int ac = ((lane >> 4) + 2 * s2) * 8;
            #pragma unroll
            for (int mt = 0; mt < 4; ++mt) {
                const uint32_t off = (uint32_t)((ar + mt * 16) * LDS_ + ac) * 2;
                ldsm4(ahi[mt], stA + off);
                ldsm4(alo[mt], stAlo + off);
            }
            const int br = wn + ((lane >> 4) & 1) * 8 + (lane & 7);
            const int bc = (((lane >> 3) & 1) + 2 * s2) * 8;
            #pragma unroll
            for (int p = 0; p < 2; ++p) {
                const uint32_t off = (uint32_t)((br + p * 16) * LDS_ + bc) * 2;
                uint32_t r4[4];
                ldsm4(r4, stB + off);
                bhi[2 * p][0] = r4[0]; bhi[2 * p][1] = r4[1];
                bhi[2 * p + 1][0] = r4[2]; bhi[2 * p + 1][1] = r4[3];
                ldsm4(r4, stBlo + off);
                blo[2 * p][0] = r4[0]; blo[2 * p][1] = r4[1];
                blo[2 * p + 1][0] = r4[2]; blo[2 * p + 1][1] = r4[3];
            }
            #pragma unroll
            for (int mt = 0; mt < 4; ++mt)
                #pragma unroll
                for (int nt = 0; nt < 4; ++nt) {
                    mma16816(acc[mt][nt], ahi[mt], bhi[nt]);
                    mma16816(acc[mt][nt], ahi[mt], blo[nt]);
                    mma16816(acc[mt][nt], alo[mt], bhi[nt]);
                }
        }
        __syncthreads();
    }
}

// ---------------------------------------------------------------------------
// Pass 1: masked scores (pre-softmax) into w
// ---------------------------------------------------------------------------
__global__ __launch_bounds__(256, 1) void scores_mma_kernel(float* __restrict__ w) {
    const int b = blockIdx.z, ti = blockIdx.y, tj = blockIdx.x;
    float* wb = w + (size_t)b * T_ * T_;
    const int gi0 = ti * 128, gj0 = tj * 128;
    const int tid = threadIdx.x;

    if (tj > ti) {  // fully masked tile
        const float4 nv = make_float4(NEG_INF_, NEG_INF_, NEG_INF_, NEG_INF_);
        #pragma unroll
        for (int t = 0; t < 16; ++t) {
            const int i = tid + t * 256;
            const int r = i >> 5, c4 = i & 31;
            *(float4*)(wb + (size_t)(gi0 + r) * T_ + gj0 + c4 * 4) = nv;
        }
        return;
    }

    float acc[4][4][4] = {};
    const size_t ao = ((size_t)b * T_ + gi0) * D_;
    const size_t bo = ((size_t)b * T_ + gj0) * D_;
    gemm_mainloop(g_xhi + ao, g_xlo + ao, g_xhi + bo, g_xlo + bo, D_, D_, acc);

    const int lane = tid & 31, warp = tid >> 5;
    const int wm = (warp >> 2) * 64, wn = (warp & 3) * 32;
    const bool diag = (ti == tj);
    #pragma unroll
    for (int mt = 0; mt < 4; ++mt)
        #pragma unroll
        for (int nt = 0; nt < 4; ++nt) {
            const int gi = gi0 + wm + mt * 16 + (lane >> 2);
            const int gj = gj0 + wn + nt * 8 + 2 * (lane & 3);
            float* p0 = wb + (size_t)gi * T_ + gj;
            float* p1 = wb + (size_t)(gi + 8) * T_ + gj;
            if (!diag) {
                p0[0] = acc[mt][nt][0]; p0[1] = acc[mt][nt][1];
                p1[0] = acc[mt][nt][2]; p1[1] = acc[mt][nt][3];
            } else {
                p0[0] = (gj     < gi    ) ? acc[mt][nt][0] : NEG_INF_;
                p0[1] = (gj + 1 < gi    ) ? acc[mt][nt][1] : NEG_INF_;
                p1[0] = (gj     < gi + 8) ? acc[mt][nt][2] : NEG_INF_;
                p1[1] = (gj + 1 < gi + 8) ? acc[mt][nt][3] : NEG_INF_;
            }
        }
}

// ---------------------------------------------------------------------------
// Pass 2: row softmax in place; also emit bf16 hi/lo of W
// ---------------------------------------------------------------------------
__global__ __launch_bounds__(256) void softmax_kernel(float* __restrict__ w) {
    const size_t row = blockIdx.x;            // 0 .. B*T-1
    float* p = w + row * T_;
    __nv_bfloat16* ph = g_whi + row * T_;
    __nv_bfloat16* pl = g_wlo + row * T_;
    const int tid = threadIdx.x;

    float v[8];
    float m = -INFINITY;
    #pragma unroll
    for (int k = 0; k < 8; ++k) { v[k] = p[tid + k * 256]; m = fmaxf(m, v[k]); }

    __shared__ float red[256];
    red[tid] = m; __syncthreads();
    #pragma unroll
    for (int s = 128; s > 0; s >>= 1) {
        if (tid < s) red[tid] = fmaxf(red[tid], red[tid + s]);
        __syncthreads();
    }
    m = red[0];
    __syncthreads();

    float sum = 0.0f;
    #pragma unroll
    for (int k = 0; k < 8; ++k) { v[k] = expf(v[k] - m); sum += v[k]; }

    red[tid] = sum; __syncthreads();
    #pragma unroll
    for (int s = 128; s > 0; s >>= 1) {
        if (tid < s) red[tid] += red[tid + s];
        __syncthreads();
    }
    const float inv = 1.0f / red[0];

    #pragma unroll
    for (int k = 0; k < 8; ++k) {
        const float val = v[k] * inv;
        p[tid + k * 256] = val;
        const __nv_bfloat16 hi = __float2bfloat16_rn(val);
        ph[tid + k * 256] = hi;
        pl[tid + k * 256] = __float2bfloat16_rn(val - __bfloat162float(hi));
    }
}

// ---------------------------------------------------------------------------
// Pass 3: att_vec = W @ X  (K truncated by causal zero structure)
// ---------------------------------------------------------------------------
__global__ __launch_bounds__(256, 1) void av_mma_kernel(float* __restrict__ o) {
    const int b = blockIdx.z, ti = blockIdx.y, tj = blockIdx.x;
    const int gi0 = ti * 128, gj0 = tj * 128;
    const int kmax = (ti == 0) ? T_ : (ti + 1) * 128;  // row 0 is dense (uniform 1/T)

    float acc[4][4][4] = {};
    const size_t ao = ((size_t)b * T_ + gi0) * T_;
    const size_t bo = ((size_t)b * D_ + gj0) * T_;
    gemm_mainloop(g_whi + ao, g_wlo + ao, g_xthi + bo, g_xtlo + bo, T_, kmax, acc);

    float* ob = o + (size_t)b * T_ * D_;
    const int tid = threadIdx.x;
    const int lane = tid & 31, warp = tid >> 5;
    const int wm = (warp >> 2) * 64, wn = (warp & 3) * 32;
    #pragma unroll
    for (int mt = 0; mt < 4; ++mt)
        #pragma unroll
        for (int nt = 0; nt < 4; ++nt) {
            const int gi = gi0 + wm + mt * 16 + (lane >> 2);
            const int gj = gj0 + wn + nt * 8 + 2 * (lane & 3);
            float* p0 = ob + (size_t)gi * D_ + gj;
            float* p1 = ob + (size_t)(gi + 8) * D_ + gj;
            p0[0] = acc[mt][nt][0]; p0[1] = acc[mt][nt][1];
            p1[0] = acc[mt][nt][2]; p1[1] = acc[mt][nt][3];
        }
}

// ---------------------------------------------------------------------------
extern "C" void kernel_launch(void* const* d_in, const int* in_sizes, int n_in,
                              void* d_out, int out_size) {
    const float* x = (const float*)d_in[0];
    float* att_vec = (float*)d_out;                          // [B,T,D]
    float* att_w   = (float*)d_out + (size_t)B_ * T_ * D_;   // [B,T,T]
    (void)in_sizes; (void)n_in; (void)out_size;

    cudaFuncSetAttribute(scores_mma_kernel, cudaFuncAttributeMaxDynamicSharedMemorySize, SMEM_BYTES);
    cudaFuncSetAttribute(av_mma_kernel, cudaFuncAttributeMaxDynamicSharedMemorySize, SMEM_BYTES);

    convert_kernel<<<dim3(D_ / 32, T_ / 32, B_), dim3(32, 8)>>>(x);
    scores_mma_kernel<<<dim3(T_ / 128, T_ / 128, B_), 256, SMEM_BYTES>>>(att_w);
    softmax_kernel<<<B_ * T_, 256>>>(att_w);
    av_mma_kernel<<<dim3(D_ / 128, T_ / 128, B_), 256, SMEM_BYTES>>>(att_vec);
}

// round 3
// speedup vs baseline: 3.1810x; 1.0679x over previous
#include <cuda_runtime.h>
#include <cuda_bf16.h>
#include <math.h>
#include <stdint.h>

// Attention_33492154974379:  x [B=8, T=2048, D=1024] fp32
// out = concat(att_vec [B,T,D], att_weights [B,T,T])
// scores = x@x^T, strict-lower kept, diag+upper=-1e9, softmax, av = W@x.
// bf16 hi/lo split (3-term) tensor-core GEMMs, fp32 accumulate.
// R3: __launch_bounds__(256,2) on MMA kernels -> 2 CTAs/SM (was reg-capped at 1).

#define B_ 8
#define T_ 2048
#define D_ 1024
#define NEG_INF_ (-1.0e9f)

// ---- static scratch (allocation-free rule: __device__ globals) ----
__device__ __nv_bfloat16 g_xhi[(size_t)B_ * T_ * D_];
__device__ __nv_bfloat16 g_xlo[(size_t)B_ * T_ * D_];
__device__ __nv_bfloat16 g_xthi[(size_t)B_ * D_ * T_];   // x^T  [B,D,T]
__device__ __nv_bfloat16 g_xtlo[(size_t)B_ * D_ * T_];
__device__ __nv_bfloat16 g_whi[(size_t)B_ * T_ * T_];
__device__ __nv_bfloat16 g_wlo[(size_t)B_ * T_ * T_];

// ---- smem geometry: 4 tiles (Ahi,Alo,Bhi,Blo) of 128 x 32 bf16, stride 40 ----
#define LDS_ 40
#define TILE_E (128 * LDS_)      // 5120 elems
#define STAGE_E (4 * TILE_E)     // 20480 elems
#define SMEM_BYTES (2 * STAGE_E * 2)  // 81920 bytes (double buffered)

__device__ __forceinline__ void ldsm4(uint32_t* r, uint32_t a) {
    asm volatile("ldmatrix.sync.aligned.m8n8.x4.shared.b16 {%0,%1,%2,%3}, [%4];"
                 : "=r"(r[0]), "=r"(r[1]), "=r"(r[2]), "=r"(r[3]) : "r"(a));
}
__device__ __forceinline__ void mma16816(float* d, const uint32_t* a, const uint32_t* b) {
    asm volatile("mma.sync.aligned.m16n8k16.row.col.f32.bf16.bf16.f32 "
                 "{%0,%1,%2,%3}, {%4,%5,%6,%7}, {%8,%9}, {%0,%1,%2,%3};"
                 : "+f"(d[0]), "+f"(d[1]), "+f"(d[2]), "+f"(d[3])
                 : "r"(a[0]), "r"(a[1]), "r"(a[2]), "r"(a[3]), "r"(b[0]), "r"(b[1]));
}
__device__ __forceinline__ void cpa16(uint32_t d, const void* s) {
    asm volatile("cp.async.cg.shared.global [%0], [%1], 16;" :: "r"(d), "l"(s) : "memory");
}
__device__ __forceinline__ void cpcommit() { asm volatile("cp.async.commit_group;" ::: "memory"); }
template <int N>
__device__ __forceinline__ void cpwait() { asm volatile("cp.async.wait_group %0;" :: "n"(N) : "memory"); }

// ---------------------------------------------------------------------------
// Pass 0: x -> (hi,lo) and transposed (hi,lo)
// ---------------------------------------------------------------------------
__global__ __launch_bounds__(256) void convert_kernel(const float* __restrict__ x) {
    __shared__ float tile[32][33];
    const int b = blockIdx.z;
    const int t0 = blockIdx.y * 32, d0 = blockIdx.x * 32;
    const int tx = threadIdx.x, ty = threadIdx.y;  // (32, 8)
    const float* xb = x + (size_t)b * T_ * D_;

    #pragma unroll
    for (int k = 0; k < 4; ++k) {
        const int r = ty + k * 8;
        const float v = xb[(size_t)(t0 + r) * D_ + d0 + tx];
        tile[r][tx] = v;
        __nv_bfloat16 hi = __float2bfloat16_rn(v);
        __nv_bfloat16 lo = __float2bfloat16_rn(v - __bfloat162float(hi));
        const size_t o = (size_t)b * T_ * D_ + (size_t)(t0 + r) * D_ + d0 + tx;
        g_xhi[o] = hi; g_xlo[o] = lo;
    }
    __syncthreads();
    #pragma unroll
    for (int k = 0; k < 4; ++k) {
        const int r = ty + k * 8;                 // local d index
        const float v = tile[tx][r];              // (d = d0+r, t = t0+tx)
        __nv_bfloat16 hi = __float2bfloat16_rn(v);
        __nv_bfloat16 lo = __float2bfloat16_rn(v - __bfloat162float(hi));
        const size_t o = (size_t)b * D_ * T_ + (size_t)(d0 + r) * T_ + t0 + tx;
        g_xthi[o] = hi; g_xtlo[o] = lo;
    }
}

// ---------------------------------------------------------------------------
// Shared MMA mainloop: C[128x128] += 3-term split GEMM over K (chunks of 32).
// A,B row-major [rows][K] with leading dim ldk; B holds the [N][K] operand.
// ---------------------------------------------------------------------------
__device__ __forceinline__ void gemm_mainloop(
    const __nv_bfloat16* __restrict__ Ahi, const __nv_bfloat16* __restrict__ Alo,
    const __nv_bfloat16* __restrict__ Bhi, const __nv_bfloat16* __restrict__ Blo,
    int ldk, int kmax, float acc[4][4][4])
{
    extern __shared__ __nv_bfloat16 sm[];
    const int tid = threadIdx.x;
    const int lane = tid & 31, warp = tid >> 5;
    const int wm = (warp >> 2) * 64, wn = (warp & 3) * 32;
    const uint32_t smem_u32 = (uint32_t)__cvta_generic_to_shared(sm);

    // copy mapping: threads [0..63]->tile0, [64..127]->tile1, ...
    const int tile = tid >> 6;
    const __nv_bfloat16* sp = (tile == 0) ? Ahi : (tile == 1) ? Alo : (tile == 2) ? Bhi : Blo;
    const int crow0 = (tid & 63) >> 2;  // + t*16
    const int cc = tid & 3;
    const uint32_t dtile = (uint32_t)(tile * TILE_E) * 2;

    const int nchunks = kmax >> 5;

    // prologue: stage 0
    {
        #pragma unroll
        for (int t = 0; t < 8; ++t) {
            const int row = crow0 + t * 16;
            cpa16(smem_u32 + dtile + (uint32_t)(row * LDS_ + cc * 8) * 2,
                  sp + (size_t)row * ldk + cc * 8);
        }
        cpcommit();
    }

    for (int i = 0; i < nchunks; ++i) {
        const int s = i & 1;
        if (i + 1 < nchunks) {
            const int kk = (i + 1) << 5;
            const uint32_t dst0 = smem_u32 + (uint32_t)((s ^ 1) * STAGE_E) * 2 + dtile;
            #pragma unroll
            for (int t = 0; t < 8; ++t) {
                const int row = crow0 + t * 16;
                cpa16(dst0 + (uint32_t)(row * LDS_ + cc * 8) * 2,
                      sp + (size_t)row * ldk + kk + cc * 8);
            }
            cpcommit();
            cpwait<1>();
        } else {
            cpwait<0>();
        }
        __syncthreads();

        const uint32_t stA   = smem_u32 + (uint32_t)(s * STAGE_E) * 2;
        const uint32_t stAlo = stA + TILE_E * 2;
        const uint32_t stB   = stA + 2 * TILE_E * 2;
        const uint32_t stBlo = stA + 3 * TILE_E * 2;

        #pragma unroll
        for (int s2 = 0; s2 < 2; ++s2) {
            uint32_t ahi[4][4], alo[4][4], bhi[4][2], blo[4][2];
            const int ar = wm + (lane & 15);
            const int ac = ((lane >> 4) + 2 * s2) * 8;
            #pragma unroll
            for (int mt = 0; mt < 4; ++mt) {
                const uint32_t off = (uint32_t)((ar + mt * 16) * LDS_ + ac) * 2;
                ldsm4(ahi[mt], stA + off);
                ldsm4(alo[mt], stAlo + off);
            }
            const int br = wn + ((lane >> 4) & 1) * 8 + (lane & 7);
            const int bc = (((lane >> 3) & 1) + 2 * s2) * 8;
            #pragma unroll
            for (int p = 0; p < 2; ++p) {
                const uint32_t off = (uint32_t)((br + p * 16) * LDS_ + bc) * 2;
                uint32_t r4[4];
                ldsm4(r4, stB + off);
                bhi[2 * p][0] = r4[0]; bhi[2 * p][1] = r4[1];
                bhi[2 * p + 1][0] = r4[2]; bhi[2 * p + 1][1] = r4[3];
                ldsm4(r4, stBlo + off);
                blo[2 * p][0] = r4[0]; blo[2 * p][1] = r4[1];
                blo[2 * p + 1][0] = r4[2]; blo[2 * p + 1][1] = r4[3];
            }
            #pragma unroll
            for (int mt = 0; mt < 4; ++mt)
                #pragma unroll
                for (int nt = 0; nt < 4; ++nt) {
                    mma16816(acc[mt][nt], ahi[mt], bhi[nt]);
                    mma16816(acc[mt][nt], ahi[mt], blo[nt]);
                    mma16816(acc[mt][nt], alo[mt], bhi[nt]);
                }
        }
        __syncthreads();
    }
}

// ---------------------------------------------------------------------------
// Pass 1: masked scores (pre-softmax) into w
// ---------------------------------------------------------------------------
__global__ __launch_bounds__(256, 2) void scores_mma_kernel(float* __restrict__ w) {
    const int b = blockIdx.z, ti = blockIdx.y, tj = blockIdx.x;
    float* wb = w + (size_t)b * T_ * T_;
    const int gi0 = ti * 128, gj0 = tj * 128;
    const int tid = threadIdx.x;

    if (tj > ti) {  // fully masked tile
        const float4 nv = make_float4(NEG_INF_, NEG_INF_, NEG_INF_, NEG_INF_);
        #pragma unroll
        for (int t = 0; t < 16; ++t) {
            const int i = tid + t * 256;
            const int r = i >> 5, c4 = i & 31;
            *(float4*)(wb + (size_t)(gi0 + r) * T_ + gj0 + c4 * 4) = nv;
        }
        return;
    }

    float acc[4][4][4] = {};
    const size_t ao = ((size_t)b * T_ + gi0) * D_;
    const size_t bo = ((size_t)b * T_ + gj0) * D_;
    gemm_mainloop(g_xhi + ao, g_xlo + ao, g_xhi + bo, g_xlo + bo, D_, D_, acc);

    const int lane = tid & 31, warp = tid >> 5;
    const int wm = (warp >> 2) * 64, wn = (warp & 3) * 32;
    const bool diag = (ti == tj);
    #pragma unroll
    for (int mt = 0; mt < 4; ++mt)
        #pragma unroll
        for (int nt = 0; nt < 4; ++nt) {
            const int gi = gi0 + wm + mt * 16 + (lane >> 2);
            const int gj = gj0 + wn + nt * 8 + 2 * (lane & 3);
            float* p0 = wb + (size_t)gi * T_ + gj;
            float* p1 = wb + (size_t)(gi + 8) * T_ + gj;
            if (!diag) {
                p0[0] = acc[mt][nt][0]; p0[1] = acc[mt][nt][1];
                p1[0] = acc[mt][nt][2]; p1[1] = acc[mt][nt][3];
            } else {
                p0[0] = (gj     < gi    ) ? acc[mt][nt][0] : NEG_INF_;
                p0[1] = (gj + 1 < gi    ) ? acc[mt][nt][1] : NEG_INF_;
                p1[0] = (gj     < gi + 8) ? acc[mt][nt][2] : NEG_INF_;
                p1[1] = (gj + 1 < gi + 8) ? acc[mt][nt][3] : NEG_INF_;
            }
        }
}

// ---------------------------------------------------------------------------
// Pass 2: row softmax in place; also emit bf16 hi/lo of W
// ---------------------------------------------------------------------------
__global__ __launch_bounds__(256) void softmax_kernel(float* __restrict__ w) {
    const size_t row = blockIdx.x;            // 0 .. B*T-1
    float* p = w + row * T_;
    __nv_bfloat16* ph = g_whi + row * T_;
    __nv_bfloat16* pl = g_wlo + row * T_;
    const int tid = threadIdx.x;

    float v[8];
    float m = -INFINITY;
    #pragma unroll
    for (int k = 0; k < 8; ++k) { v[k] = p[tid + k * 256]; m = fmaxf(m, v[k]); }

    __shared__ float red[256];
    red[tid] = m; __syncthreads();
    #pragma unroll
    for (int s = 128; s > 0; s >>= 1) {
        if (tid < s) red[tid] = fmaxf(red[tid], red[tid + s]);
        __syncthreads();
    }
    m = red[0];
    __syncthreads();

    float sum = 0.0f;
    #pragma unroll
    for (int k = 0; k < 8; ++k) { v[k] = expf(v[k] - m); sum += v[k]; }

    red[tid] = sum; __syncthreads();
    #pragma unroll
    for (int s = 128; s > 0; s >>= 1) {
        if (tid < s) red[tid] += red[tid + s];
        __syncthreads();
    }
    const float inv = 1.0f / red[0];

    #pragma unroll
    for (int k = 0; k < 8; ++k) {
        const float val = v[k] * inv;
        p[tid + k * 256] = val;
        const __nv_bfloat16 hi = __float2bfloat16_rn(val);
        ph[tid + k * 256] = hi;
        pl[tid + k * 256] = __float2bfloat16_rn(val - __bfloat162float(hi));
    }
}

// ---------------------------------------------------------------------------
// Pass 3: att_vec = W @ X  (K truncated by causal zero structure)
// ---------------------------------------------------------------------------
__global__ __launch_bounds__(256, 2) void av_mma_kernel(float* __restrict__ o) {
    const int b = blockIdx.z, ti = blockIdx.y, tj = blockIdx.x;
    const int gi0 = ti * 128, gj0 = tj * 128;
    const int kmax = (ti == 0) ? T_ : (ti + 1) * 128;  // row 0 is dense (uniform 1/T)

    float acc[4][4][4] = {};
    const size_t ao = ((size_t)b * T_ + gi0) * T_;
    const size_t bo = ((size_t)b * D_ + gj0) * T_;
    gemm_mainloop(g_whi + ao, g_wlo + ao, g_xthi + bo, g_xtlo + bo, T_, kmax, acc);

    float* ob = o + (size_t)b * T_ * D_;
    const int tid = threadIdx.x;
    const int lane = tid & 31, warp = tid >> 5;
    const int wm = (warp >> 2) * 64, wn = (warp & 3) * 32;
    #pragma unroll
    for (int mt = 0; mt < 4; ++mt)
        #pragma unroll
        for (int nt = 0; nt < 4; ++nt) {
            const int gi = gi0 + wm + mt * 16 + (lane >> 2);
            const int gj = gj0 + wn + nt * 8 + 2 * (lane & 3);
            float* p0 = ob + (size_t)gi * D_ + gj;
            float* p1 = ob + (size_t)(gi + 8) * D_ + gj;
            p0[0] = acc[mt][nt][0]; p0[1] = acc[mt][nt][1];
            p1[0] = acc[mt][nt][2]; p1[1] = acc[mt][nt][3];
        }
}

// ---------------------------------------------------------------------------
extern "C" void kernel_launch(void* const* d_in, const int* in_sizes, int n_in,
                              void* d_out, int out_size) {
    const float* x = (const float*)d_in[0];
    float* att_vec = (float*)d_out;                          // [B,T,D]
    float* att_w   = (float*)d_out + (size_t)B_ * T_ * D_;   // [B,T,T]
    (void)in_sizes; (void)n_in; (void)out_size;

    cudaFuncSetAttribute(scores_mma_kernel, cudaFuncAttributeMaxDynamicSharedMemorySize, SMEM_BYTES);
    cudaFuncSetAttribute(av_mma_kernel, cudaFuncAttributeMaxDynamicSharedMemorySize, SMEM_BYTES);

    convert_kernel<<<dim3(D_ / 32, T_ / 32, B_), dim3(32, 8)>>>(x);
    scores_mma_kernel<<<dim3(T_ / 128, T_ / 128, B_), 256, SMEM_BYTES>>>(att_w);
    softmax_kernel<<<B_ * T_, 256>>>(att_w);
    av_mma_kernel<<<dim3(D_ / 128, T_ / 128, B_), 256, SMEM_BYTES>>>(att_vec);
}